// round 1
// baseline (speedup 1.0000x reference)
#include <cuda_runtime.h>
#include <math.h>

#define B_SAMPLES 128
#define T_LEN     8192
#define C_CLASSES 64
#define TILE      128     // positions per K1 CTA
#define K1_THREADS 128
#define PAD       65      // padded row stride (floats) -> conflict-free compute reads
#define K2_THREADS 256
#define OUT_LEN   8

// Scratch (allocation-free: __device__ globals)
__device__ float         g_conf[B_SAMPLES * T_LEN];
__device__ unsigned char g_pred[B_SAMPLES * T_LEN];

// ---------------------------------------------------------------------------
// K1: per-position softmax confidence + argmax.
// One CTA = 128 positions of one sample. Stage 128x64 f32 tile in smem,
// thread-per-position compute (pad-65 rows => bank-conflict-free LDS reads).
// ---------------------------------------------------------------------------
__global__ __launch_bounds__(K1_THREADS)
void softmax_conf_kernel(const float* __restrict__ x) {
    __shared__ float sx[TILE * PAD];   // 33280 B

    const int b  = blockIdx.y;
    const int t0 = blockIdx.x * TILE;
    const size_t base = ((size_t)b * T_LEN + t0) * C_CLASSES;

    // Cooperative coalesced load: TILE*C/4 = 2048 float4s, 128 threads.
    const float4* __restrict__ xv = (const float4*)(x + base);
    #pragma unroll
    for (int i = threadIdx.x; i < (TILE * C_CLASSES) / 4; i += K1_THREADS) {
        float4 v = xv[i];
        int p = i >> 4;            // 16 float4 per 64-class row
        int c = (i & 15) * 4;
        float* row = sx + p * PAD + c;
        row[0] = v.x; row[1] = v.y; row[2] = v.z; row[3] = v.w;
    }
    __syncthreads();

    const int p = threadIdx.x;                 // one position per thread
    const float* __restrict__ row = sx + p * PAD;

    // Pass 1: max + argmax (first occurrence on tie, matching jnp.argmax)
    float m = row[0];
    int   am = 0;
    #pragma unroll 16
    for (int c = 1; c < C_CLASSES; c++) {
        float v = row[c];
        if (v > m) { m = v; am = c; }
    }

    // Pass 2: sum of exp(x - max); conf = 1/sum (== max softmax prob)
    float s = 0.0f;
    #pragma unroll 16
    for (int c = 0; c < C_CLASSES; c++) {
        s += expf(row[c] - m);
    }
    float conf = 1.0f / s;

    size_t o = (size_t)b * T_LEN + t0 + p;
    g_conf[o] = conf;
    g_pred[o] = (unsigned char)am;
}

// ---------------------------------------------------------------------------
// K2: per-sample run-length encoding + top-8 by voted confidence.
// One CTA per sample. voted[t] = conf[t]*run_len at run starts, -inf elsewhere.
// Top-8 via 8 rounds of block argmax (ties -> lowest index == lax.top_k).
// ---------------------------------------------------------------------------
__global__ __launch_bounds__(K2_THREADS)
void topk_kernel(float* __restrict__ out) {
    __shared__ float         voted[T_LEN];          // 32 KB
    __shared__ unsigned char spred[T_LEN];          //  8 KB
    __shared__ float rv[K2_THREADS];
    __shared__ int   ri[K2_THREADS];
    __shared__ float resv[OUT_LEN];
    __shared__ int   resi[OUT_LEN];

    const int b = blockIdx.x;
    const size_t off = (size_t)b * T_LEN;

    for (int t = threadIdx.x; t < T_LEN; t += K2_THREADS)
        spred[t] = g_pred[off + t];
    __syncthreads();

    for (int t = threadIdx.x; t < T_LEN; t += K2_THREADS) {
        bool start = (t == 0) || (spred[t] != spred[t - 1]);
        float v = -INFINITY;
        if (start) {
            unsigned char pv = spred[t];
            int j = t + 1;
            while (j < T_LEN && spred[j] == pv) j++;   // runs avg ~1.02 long
            v = g_conf[off + t] * (float)(j - t);
        }
        voted[t] = v;
    }
    __syncthreads();

    for (int k = 0; k < OUT_LEN; k++) {
        float bv = -INFINITY;
        int   bi = T_LEN;   // invalid sentinel, larger than any real index
        for (int t = threadIdx.x; t < T_LEN; t += K2_THREADS) {
            float v = voted[t];
            if (v > bv || (v == bv && t < bi)) { bv = v; bi = t; }
        }
        rv[threadIdx.x] = bv;
        ri[threadIdx.x] = bi;
        __syncthreads();
        for (int s = K2_THREADS / 2; s > 0; s >>= 1) {
            if (threadIdx.x < s) {
                float ov = rv[threadIdx.x + s];
                int   oi = ri[threadIdx.x + s];
                if (ov > rv[threadIdx.x] ||
                    (ov == rv[threadIdx.x] && oi < ri[threadIdx.x])) {
                    rv[threadIdx.x] = ov;
                    ri[threadIdx.x] = oi;
                }
            }
            __syncthreads();
        }
        if (threadIdx.x == 0) {
            resv[k] = rv[0];
            resi[k] = ri[0];
            if (ri[0] < T_LEN) voted[ri[0]] = -INFINITY;  // remove selected
        }
        __syncthreads();
    }

    if (threadIdx.x < OUT_LEN) {
        float v = resv[threadIdx.x];
        int   i = resi[threadIdx.x];
        float o = 0.0f;                      // pad-with-zero path
        if (isfinite(v) && i < T_LEN) o = (float)spred[i];
        out[(size_t)b * OUT_LEN + threadIdx.x] = o;
    }
}

// ---------------------------------------------------------------------------
extern "C" void kernel_launch(void* const* d_in, const int* in_sizes, int n_in,
                              void* d_out, int out_size) {
    const float* x = (const float*)d_in[0];
    float* out = (float*)d_out;

    dim3 g1(T_LEN / TILE, B_SAMPLES);     // 64 x 128 CTAs
    softmax_conf_kernel<<<g1, K1_THREADS>>>(x);
    topk_kernel<<<B_SAMPLES, K2_THREADS>>>(out);
}

// round 2
// speedup vs baseline: 1.6288x; 1.6288x over previous
#include <cuda_runtime.h>
#include <math.h>

#define B_SAMPLES 128
#define T_LEN     8192
#define C_CLASSES 64
#define OUT_LEN   8

#define K1_THREADS 256
#define POS_PER_CTA (K1_THREADS / 4)     // 4 threads per position
#define K2_THREADS 1024
#define ELEMS_PER_THREAD (T_LEN / K2_THREADS)   // 8

// Scratch (allocation-free __device__ globals)
__device__ __align__(16) float         g_conf[B_SAMPLES * T_LEN];
__device__ __align__(16) unsigned char g_pred[B_SAMPLES * T_LEN];

// ---------------------------------------------------------------------------
// K1: softmax confidence (max prob) + argmax, 4 threads per position, regs only.
// Warp covers 8 positions = 2KB contiguous global reads (4x LDG.128 / thread).
// ---------------------------------------------------------------------------
__global__ __launch_bounds__(K1_THREADS)
void softmax_conf_kernel(const float* __restrict__ x) {
    const int tid  = threadIdx.x;
    const int part = tid & 3;            // which 16-class chunk
    const size_t pos = (size_t)blockIdx.x * POS_PER_CTA + (tid >> 2);

    const float4* __restrict__ p =
        (const float4*)(x + pos * C_CLASSES + part * 16);
    float4 v0 = p[0], v1 = p[1], v2 = p[2], v3 = p[3];

    float r[16] = {v0.x, v0.y, v0.z, v0.w, v1.x, v1.y, v1.z, v1.w,
                   v2.x, v2.y, v2.z, v2.w, v3.x, v3.y, v3.z, v3.w};

    // Local max + first-occurrence argmax over this 16-chunk
    float m = r[0];
    int   am = 0;
    #pragma unroll
    for (int c = 1; c < 16; c++)
        if (r[c] > m) { m = r[c]; am = c; }
    int amg = part * 16 + am;

    // Combine max/argmax across the 4 cooperating lanes (xor 1,2 stays in group)
    #pragma unroll
    for (int d = 1; d < 4; d <<= 1) {
        float om = __shfl_xor_sync(0xFFFFFFFFu, m,   d);
        int   oa = __shfl_xor_sync(0xFFFFFFFFu, amg, d);
        if (om > m || (om == m && oa < amg)) { m = om; amg = oa; }
    }

    // Sum of exp(x - max), reduced across the 4 lanes
    float s = 0.0f;
    #pragma unroll
    for (int c = 0; c < 16; c++)
        s += expf(r[c] - m);
    #pragma unroll
    for (int d = 1; d < 4; d <<= 1)
        s += __shfl_xor_sync(0xFFFFFFFFu, s, d);

    if (part == 0) {
        g_conf[pos] = 1.0f / s;
        g_pred[pos] = (unsigned char)amg;
    }
}

// ---------------------------------------------------------------------------
// K2: per-sample RLE + top-8 by voted confidence. One CTA (1024 thr) per sample.
// voted lives in REGISTERS (8/thread); rounds = reg scan + 2-level shfl argmax.
// ---------------------------------------------------------------------------
__global__ __launch_bounds__(K2_THREADS)
void topk_kernel(float* __restrict__ out) {
    __shared__ unsigned char spred[T_LEN];      // 8 KB
    __shared__ float wv[32];
    __shared__ int   wi[32];
    __shared__ float outv[OUT_LEN];
    __shared__ int   outi[OUT_LEN];

    const int b   = blockIdx.x;
    const int tid = threadIdx.x;
    const size_t off = (size_t)b * T_LEN;

    // Coalesced 8B-per-thread pred load
    ((uint2*)spred)[tid] = ((const uint2*)(g_pred + off))[tid];
    __syncthreads();

    // voted[t] for t = tid + j*1024 (strided -> coalesced conf loads)
    float lv[ELEMS_PER_THREAD];
    #pragma unroll
    for (int j = 0; j < ELEMS_PER_THREAD; j++) {
        int t = tid + j * K2_THREADS;
        bool start = (t == 0) || (spred[t] != spred[t - 1]);
        float v = -INFINITY;
        if (start) {
            unsigned char pv = spred[t];
            int e = t + 1;
            while (e < T_LEN && spred[e] == pv) e++;   // runs avg ~1.02
            v = g_conf[off + t] * (float)(e - t);
        }
        lv[j] = v;
    }

    const int lane = tid & 31;
    const int wid  = tid >> 5;

    for (int k = 0; k < OUT_LEN; k++) {
        // Local argmax over 8 regs (j ascending = t ascending -> first-max tie)
        float bv = lv[0];
        int   bj = 0;
        #pragma unroll
        for (int j = 1; j < ELEMS_PER_THREAD; j++)
            if (lv[j] > bv) { bv = lv[j]; bj = j; }
        int bi = tid + bj * K2_THREADS;

        // Warp argmax (ties -> lowest index, matching lax.top_k)
        #pragma unroll
        for (int d = 16; d > 0; d >>= 1) {
            float ov = __shfl_xor_sync(0xFFFFFFFFu, bv, d);
            int   oi = __shfl_xor_sync(0xFFFFFFFFu, bi, d);
            if (ov > bv || (ov == bv && oi < bi)) { bv = ov; bi = oi; }
        }
        if (lane == 0) { wv[wid] = bv; wi[wid] = bi; }
        __syncthreads();

        // Cross-warp argmax in warp 0
        if (wid == 0) {
            float v2 = wv[lane];
            int   i2 = wi[lane];
            #pragma unroll
            for (int d = 16; d > 0; d >>= 1) {
                float ov = __shfl_xor_sync(0xFFFFFFFFu, v2, d);
                int   oi = __shfl_xor_sync(0xFFFFFFFFu, i2, d);
                if (ov > v2 || (ov == v2 && oi < i2)) { v2 = ov; i2 = oi; }
            }
            if (lane == 0) { outv[k] = v2; outi[k] = i2; }
        }
        __syncthreads();

        // Invalidate winner in its owner's registers
        int win = outi[k];
        if ((win & (K2_THREADS - 1)) == tid)
            lv[win >> 10] = -INFINITY;
    }

    if (tid < OUT_LEN) {
        float v = outv[tid];
        int   i = outi[tid];
        float o = 0.0f;                               // pad-with-zero path
        if (isfinite(v)) o = (float)spred[i];
        out[(size_t)b * OUT_LEN + tid] = o;
    }
}

// ---------------------------------------------------------------------------
extern "C" void kernel_launch(void* const* d_in, const int* in_sizes, int n_in,
                              void* d_out, int out_size) {
    const float* x = (const float*)d_in[0];
    float* out = (float*)d_out;

    const int n_pos = B_SAMPLES * T_LEN;
    softmax_conf_kernel<<<n_pos / POS_PER_CTA, K1_THREADS>>>(x);
    topk_kernel<<<B_SAMPLES, K2_THREADS>>>(out);
}

// round 3
// speedup vs baseline: 1.6557x; 1.0165x over previous
#include <cuda_runtime.h>
#include <math.h>

#define B_SAMPLES 128
#define T_LEN     8192
#define C_CLASSES 64
#define OUT_LEN   8

#define K1_THREADS 256
#define POS_PER_CTA (K1_THREADS / 4)            // 4 threads per position
#define K2_THREADS 1024
#define ELEMS_PER_THREAD (T_LEN / K2_THREADS)   // 8

// Scratch (allocation-free __device__ globals)
__device__ __align__(16) float         g_conf[B_SAMPLES * T_LEN];
__device__ __align__(16) unsigned char g_pred[B_SAMPLES * T_LEN];

// ---------------------------------------------------------------------------
// K1: softmax confidence (max prob) + argmax, 4 threads per position, regs only.
// Warp covers 8 positions = 2KB contiguous global reads (4x LDG.128 / thread).
// ---------------------------------------------------------------------------
__global__ __launch_bounds__(K1_THREADS)
void softmax_conf_kernel(const float* __restrict__ x) {
    const int tid  = threadIdx.x;
    const int part = tid & 3;            // which 16-class chunk
    const size_t pos = (size_t)blockIdx.x * POS_PER_CTA + (tid >> 2);

    const float4* __restrict__ p =
        (const float4*)(x + pos * C_CLASSES + part * 16);
    float4 v0 = p[0], v1 = p[1], v2 = p[2], v3 = p[3];

    float r[16] = {v0.x, v0.y, v0.z, v0.w, v1.x, v1.y, v1.z, v1.w,
                   v2.x, v2.y, v2.z, v2.w, v3.x, v3.y, v3.z, v3.w};

    // Local max + first-occurrence argmax over this 16-chunk
    float m = r[0];
    int   am = 0;
    #pragma unroll
    for (int c = 1; c < 16; c++)
        if (r[c] > m) { m = r[c]; am = c; }
    int amg = part * 16 + am;

    // Combine max/argmax across the 4 cooperating lanes (xor 1,2 stays in group)
    #pragma unroll
    for (int d = 1; d < 4; d <<= 1) {
        float om = __shfl_xor_sync(0xFFFFFFFFu, m,   d);
        int   oa = __shfl_xor_sync(0xFFFFFFFFu, amg, d);
        if (om > m || (om == m && oa < amg)) { m = om; amg = oa; }
    }

    // Sum of exp(x - max), reduced across the 4 lanes
    float s = 0.0f;
    #pragma unroll
    for (int c = 0; c < 16; c++)
        s += expf(r[c] - m);
    #pragma unroll
    for (int d = 1; d < 4; d <<= 1)
        s += __shfl_xor_sync(0xFFFFFFFFu, s, d);

    if (part == 0) {
        g_conf[pos] = 1.0f / s;
        g_pred[pos] = (unsigned char)amg;
    }
}

// ---------------------------------------------------------------------------
// K2: per-sample RLE + top-8. One CTA (1024 thr) per sample.
// Phase A: per-warp top-8 (registers + shuffles, zero barriers).
// Phase B: warp 0 merges 32x8 candidates (one barrier). 2 barriers total.
// ---------------------------------------------------------------------------
__global__ __launch_bounds__(K2_THREADS)
void topk_kernel(float* __restrict__ out) {
    __shared__ unsigned char spred[T_LEN];           // 8 KB
    __shared__ float candv[OUT_LEN * 32];            // [round][warp]
    __shared__ int   candi[OUT_LEN * 32];
    __shared__ float outv[OUT_LEN];
    __shared__ int   outi[OUT_LEN];

    const int b    = blockIdx.x;
    const int tid  = threadIdx.x;
    const int lane = tid & 31;
    const int wid  = tid >> 5;
    const size_t off = (size_t)b * T_LEN;

    // Coalesced 8B-per-thread pred load
    ((uint2*)spred)[tid] = ((const uint2*)(g_pred + off))[tid];
    __syncthreads();

    // voted[t] for t = tid + j*1024 (strided -> coalesced conf loads)
    float lv[ELEMS_PER_THREAD];
    #pragma unroll
    for (int j = 0; j < ELEMS_PER_THREAD; j++) {
        int t = tid + j * K2_THREADS;
        bool start = (t == 0) || (spred[t] != spred[t - 1]);
        float v = -INFINITY;
        if (start) {
            unsigned char pv = spred[t];
            int e = t + 1;
            while (e < T_LEN && spred[e] == pv) e++;   // runs avg ~1.02
            v = g_conf[off + t] * (float)(e - t);
        }
        lv[j] = v;
    }

    // ---- Phase A: per-warp top-8 (no barriers) ----
    #pragma unroll
    for (int k = 0; k < OUT_LEN; k++) {
        // Local argmax (j ascending = index ascending -> first-max on tie)
        float bv = lv[0];
        int   bj = 0;
        #pragma unroll
        for (int j = 1; j < ELEMS_PER_THREAD; j++)
            if (lv[j] > bv) { bv = lv[j]; bj = j; }
        int bi = tid + bj * K2_THREADS;

        // Butterfly: all lanes converge to warp winner (tie -> lowest index)
        #pragma unroll
        for (int d = 16; d > 0; d >>= 1) {
            float ov = __shfl_xor_sync(0xFFFFFFFFu, bv, d);
            int   oi = __shfl_xor_sync(0xFFFFFFFFu, bi, d);
            if (ov > bv || (ov == bv && oi < bi)) { bv = ov; bi = oi; }
        }
        if (lane == 0) {
            candv[k * 32 + wid] = bv;      // conflict-free [round][warp]
            candi[k * 32 + wid] = bi;
        }
        // Owner thread invalidates its register copy (index is unique)
        if ((bi & (K2_THREADS - 1)) == tid)
            lv[bi >> 10] = -INFINITY;
    }
    __syncthreads();

    // ---- Phase B: warp 0 merges 256 candidates ----
    if (wid == 0) {
        float cv[OUT_LEN];
        int   ci[OUT_LEN];
        #pragma unroll
        for (int r = 0; r < OUT_LEN; r++) {
            cv[r] = candv[r * 32 + lane];   // conflict-free
            ci[r] = candi[r * 32 + lane];
        }
        #pragma unroll
        for (int k = 0; k < OUT_LEN; k++) {
            // Per-lane candidates are value-desc / index-asc on ties, so a
            // strict > scan keeps the lowest-index tie, matching lax.top_k.
            float bv = cv[0];
            int   bi = ci[0], br = 0;
            #pragma unroll
            for (int r = 1; r < OUT_LEN; r++)
                if (cv[r] > bv) { bv = cv[r]; bi = ci[r]; br = r; }
            float mv = bv; int mi = bi;
            #pragma unroll
            for (int d = 16; d > 0; d >>= 1) {
                float ov = __shfl_xor_sync(0xFFFFFFFFu, mv, d);
                int   oi = __shfl_xor_sync(0xFFFFFFFFu, mi, d);
                if (ov > mv || (ov == mv && oi < mi)) { mv = ov; mi = oi; }
            }
            if (lane == 0) { outv[k] = mv; outi[k] = mi; }
            // Owner lane invalidates (indices unique -> exactly one match)
            if (bi == mi) cv[br] = -INFINITY;
        }
    }
    __syncthreads();

    if (tid < OUT_LEN) {
        float v = outv[tid];
        int   i = outi[tid];
        float o = 0.0f;                               // pad-with-zero path
        if (isfinite(v)) o = (float)spred[i];
        out[(size_t)b * OUT_LEN + tid] = o;
    }
}

// ---------------------------------------------------------------------------
extern "C" void kernel_launch(void* const* d_in, const int* in_sizes, int n_in,
                              void* d_out, int out_size) {
    const float* x = (const float*)d_in[0];
    float* out = (float*)d_out;

    const int n_pos = B_SAMPLES * T_LEN;
    softmax_conf_kernel<<<n_pos / POS_PER_CTA, K1_THREADS>>>(x);
    topk_kernel<<<B_SAMPLES, K2_THREADS>>>(out);
}

// round 4
// speedup vs baseline: 1.7259x; 1.0424x over previous
#include <cuda_runtime.h>
#include <math.h>

#define B_SAMPLES 128
#define T_LEN     8192
#define C_CLASSES 64
#define OUT_LEN   8

#define K1_THREADS 256
#define POS_PER_CTA (K1_THREADS / 4)            // 4 threads per position
#define K2_THREADS 1024
#define EPT 8                                    // contiguous elems per thread

// Scratch (allocation-free __device__ globals)
__device__ __align__(16) float         g_conf[B_SAMPLES * T_LEN];
__device__ __align__(16) unsigned char g_pred[B_SAMPLES * T_LEN];

// ---------------------------------------------------------------------------
// K1: softmax confidence (max prob) + argmax, 4 threads per position, regs only.
// ---------------------------------------------------------------------------
__global__ __launch_bounds__(K1_THREADS)
void softmax_conf_kernel(const float* __restrict__ x) {
    const int tid  = threadIdx.x;
    const int part = tid & 3;            // which 16-class chunk
    const size_t pos = (size_t)blockIdx.x * POS_PER_CTA + (tid >> 2);

    const float4* __restrict__ p =
        (const float4*)(x + pos * C_CLASSES + part * 16);
    float4 v0 = p[0], v1 = p[1], v2 = p[2], v3 = p[3];

    float r[16] = {v0.x, v0.y, v0.z, v0.w, v1.x, v1.y, v1.z, v1.w,
                   v2.x, v2.y, v2.z, v2.w, v3.x, v3.y, v3.z, v3.w};

    float m = r[0];
    int   am = 0;
    #pragma unroll
    for (int c = 1; c < 16; c++)
        if (r[c] > m) { m = r[c]; am = c; }
    int amg = part * 16 + am;

    #pragma unroll
    for (int d = 1; d < 4; d <<= 1) {
        float om = __shfl_xor_sync(0xFFFFFFFFu, m,   d);
        int   oa = __shfl_xor_sync(0xFFFFFFFFu, amg, d);
        if (om > m || (om == m && oa < amg)) { m = om; amg = oa; }
    }

    float s = 0.0f;
    #pragma unroll
    for (int c = 0; c < 16; c++)
        s += expf(r[c] - m);
    #pragma unroll
    for (int d = 1; d < 4; d <<= 1)
        s += __shfl_xor_sync(0xFFFFFFFFu, s, d);

    if (part == 0) {
        g_conf[pos] = 1.0f / s;
        g_pred[pos] = (unsigned char)amg;
    }
}

// ---------------------------------------------------------------------------
// K2: per-sample RLE + top-8. One CTA (1024 thr) per sample.
// Each thread owns 8 CONTIGUOUS positions; pred(uint2) + conf(2x float4) are
// unconditional, front-batched global loads. Run scan is register-local with
// a rare smem spill past the chunk edge. Then warp top-8 + warp-0 merge.
// ---------------------------------------------------------------------------
__global__ __launch_bounds__(K2_THREADS)
void topk_kernel(float* __restrict__ out) {
    __shared__ unsigned char spred[T_LEN];           // 8 KB
    __shared__ float candv[OUT_LEN * 32];            // [round][warp]
    __shared__ int   candi[OUT_LEN * 32];
    __shared__ float outv[OUT_LEN];
    __shared__ int   outi[OUT_LEN];

    const int b    = blockIdx.x;
    const int tid  = threadIdx.x;
    const int lane = tid & 31;
    const int wid  = tid >> 5;
    const size_t off = (size_t)b * T_LEN;
    const int t0 = tid * EPT;

    // ---- Front-batched, unconditional global loads (MLP>=3) ----
    uint2  pv2 = ((const uint2*)(g_pred + off))[tid];
    float4 c0  = ((const float4*)(g_conf + off))[tid * 2];
    float4 c1  = ((const float4*)(g_conf + off))[tid * 2 + 1];

    ((uint2*)spred)[tid] = pv2;
    __syncthreads();

    unsigned char pb[EPT];
    pb[0] = (unsigned char)(pv2.x);        pb[1] = (unsigned char)(pv2.x >> 8);
    pb[2] = (unsigned char)(pv2.x >> 16);  pb[3] = (unsigned char)(pv2.x >> 24);
    pb[4] = (unsigned char)(pv2.y);        pb[5] = (unsigned char)(pv2.y >> 8);
    pb[6] = (unsigned char)(pv2.y >> 16);  pb[7] = (unsigned char)(pv2.y >> 24);
    float cf[EPT] = {c0.x, c0.y, c0.z, c0.w, c1.x, c1.y, c1.z, c1.w};

    // Byte just before this chunk (t0==0 handled by the t==0 start rule)
    unsigned char prev = (tid == 0) ? (unsigned char)(pb[0] ^ 1) : spred[t0 - 1];

    float lv[EPT];
    #pragma unroll
    for (int j = 0; j < EPT; j++) {
        unsigned char cur = pb[j];
        unsigned char before = (j == 0) ? prev : pb[j - 1];
        bool start = (t0 + j == 0) || (cur != before);
        float v = -INFINITY;
        if (start) {
            int cnt = 1;
            int jj = j + 1;
            while (jj < EPT && pb[jj] == cur) { cnt++; jj++; }   // reg scan
            if (jj == EPT) {                                      // rare spill
                int e = t0 + EPT;
                while (e < T_LEN && spred[e] == cur) { cnt++; e++; }
            }
            v = cf[j] * (float)cnt;
        }
        lv[j] = v;
    }

    // ---- Phase A: per-warp top-8 (no barriers) ----
    #pragma unroll
    for (int k = 0; k < OUT_LEN; k++) {
        float bv = lv[0];
        int   bj = 0;
        #pragma unroll
        for (int j = 1; j < EPT; j++)
            if (lv[j] > bv) { bv = lv[j]; bj = j; }   // j asc = index asc
        int bi = t0 + bj;

        #pragma unroll
        for (int d = 16; d > 0; d >>= 1) {
            float ov = __shfl_xor_sync(0xFFFFFFFFu, bv, d);
            int   oi = __shfl_xor_sync(0xFFFFFFFFu, bi, d);
            if (ov > bv || (ov == bv && oi < bi)) { bv = ov; bi = oi; }
        }
        if (lane == 0) {
            candv[k * 32 + wid] = bv;
            candi[k * 32 + wid] = bi;
        }
        if ((bi >> 3) == tid)              // owner invalidates
            lv[bi & (EPT - 1)] = -INFINITY;
    }
    __syncthreads();

    // ---- Phase B: warp 0 merges 32x8 candidates ----
    if (wid == 0) {
        float cv[OUT_LEN];
        int   ci[OUT_LEN];
        #pragma unroll
        for (int r = 0; r < OUT_LEN; r++) {
            cv[r] = candv[r * 32 + lane];
            ci[r] = candi[r * 32 + lane];
        }
        #pragma unroll
        for (int k = 0; k < OUT_LEN; k++) {
            // Per-lane candidates are value-desc / index-asc on ties, so a
            // strict > scan keeps the lowest-index tie, matching lax.top_k.
            float bv = cv[0];
            int   bi = ci[0], br = 0;
            #pragma unroll
            for (int r = 1; r < OUT_LEN; r++)
                if (cv[r] > bv) { bv = cv[r]; bi = ci[r]; br = r; }
            float mv = bv; int mi = bi;
            #pragma unroll
            for (int d = 16; d > 0; d >>= 1) {
                float ov = __shfl_xor_sync(0xFFFFFFFFu, mv, d);
                int   oi = __shfl_xor_sync(0xFFFFFFFFu, mi, d);
                if (ov > mv || (ov == mv && oi < mi)) { mv = ov; mi = oi; }
            }
            if (lane == 0) { outv[k] = mv; outi[k] = mi; }
            if (bi == mi) cv[br] = -INFINITY;   // unique index -> one owner
        }
    }
    __syncthreads();

    if (tid < OUT_LEN) {
        float v = outv[tid];
        int   i = outi[tid];
        float o = 0.0f;                               // pad-with-zero path
        if (isfinite(v)) o = (float)spred[i];
        out[(size_t)b * OUT_LEN + tid] = o;
    }
}

// ---------------------------------------------------------------------------
extern "C" void kernel_launch(void* const* d_in, const int* in_sizes, int n_in,
                              void* d_out, int out_size) {
    const float* x = (const float*)d_in[0];
    float* out = (float*)d_out;

    const int n_pos = B_SAMPLES * T_LEN;
    softmax_conf_kernel<<<n_pos / POS_PER_CTA, K1_THREADS>>>(x);
    topk_kernel<<<B_SAMPLES, K2_THREADS>>>(out);
}